// round 1
// baseline (speedup 1.0000x reference)
#include <cuda_runtime.h>
#include <cuda_bf16.h>
#include <cstddef>

// Problem constants (from reference setup_inputs):
//   B=4, S=2048, D=1024, G=256, I=1024, H=16
// Algebraic collapse: keys are broadcast-identical along the key axis, so
// softmax == 1/S exactly, and
//   out[b,s,:] = ((mean_s x[b,s,:]) @ Wv) @ Wo      (independent of s)

#define BATCH   4
#define SEQ     2048
#define DIM     1024
#define IDIM    1024
#define NSPLIT  32              // S-splits for column-sum
#define SROWS   (SEQ / NSPLIT)  // 64 rows per split
#define DSPL    8               // reduction splits inside each GEMV
#define CH      128             // output chunk per GEMV block (== DIM/DSPL)

// Scratch (no device allocation allowed -> __device__ globals)
__device__ float g_part[BATCH * NSPLIT * DIM];   // 512 KB
__device__ float g_tp  [BATCH * DSPL  * IDIM];   // 128 KB
__device__ float g_yp  [BATCH * DSPL  * DIM];    // 128 KB
__device__ float g_y   [BATCH * DIM];            // 16 KB

// ---------------------------------------------------------------------------
// K1: partial column sums of x over S.  grid (DIM/256, NSPLIT, BATCH), 256 thr
// ---------------------------------------------------------------------------
__global__ void k_colsum(const float* __restrict__ x) {
    const int d  = blockIdx.x * 256 + threadIdx.x;
    const int sp = blockIdx.y;
    const int b  = blockIdx.z;
    const float* p = x + ((size_t)(b * SEQ + sp * SROWS)) * DIM + d;
    float acc = 0.0f;
#pragma unroll 8
    for (int s = 0; s < SROWS; ++s) {
        acc += p[(size_t)s * DIM];
    }
    g_part[(b * NSPLIT + sp) * DIM + d] = acc;
}

// ---------------------------------------------------------------------------
// K2: t_part[b][ds][i] = sum_{d in ds-slice} xbar[b][d] * Wv[d][i]
//     grid (IDIM/CH, DSPL, BATCH), CH threads
// ---------------------------------------------------------------------------
__global__ void k_gemv1(const float* __restrict__ Wv) {
    __shared__ float xs[CH];
    const int b  = blockIdx.z;
    const int ds = blockIdx.y;
    const int i  = blockIdx.x * CH + threadIdx.x;
    const int d0 = ds * (DIM / DSPL);

    // Build xbar slice (mean over S) from the 32 partials — all L2 hits.
    {
        float s = 0.0f;
#pragma unroll
        for (int p = 0; p < NSPLIT; ++p)
            s += g_part[(b * NSPLIT + p) * DIM + d0 + threadIdx.x];
        xs[threadIdx.x] = s * (1.0f / (float)SEQ);
    }
    __syncthreads();

    float acc = 0.0f;
#pragma unroll 4
    for (int d = 0; d < DIM / DSPL; ++d)
        acc += xs[d] * __ldg(&Wv[(size_t)(d0 + d) * IDIM + i]);
    g_tp[(b * DSPL + ds) * IDIM + i] = acc;
}

// ---------------------------------------------------------------------------
// K3: y_part[b][is][o] = sum_{i in is-slice} t[b][i] * Wo[i][o]
//     grid (DIM/CH, DSPL, BATCH), CH threads
// ---------------------------------------------------------------------------
__global__ void k_gemv2(const float* __restrict__ Wo) {
    __shared__ float ts[CH];
    const int b  = blockIdx.z;
    const int is = blockIdx.y;
    const int o  = blockIdx.x * CH + threadIdx.x;
    const int i0 = is * (IDIM / DSPL);

    {
        float s = 0.0f;
#pragma unroll
        for (int p = 0; p < DSPL; ++p)
            s += g_tp[(b * DSPL + p) * IDIM + i0 + threadIdx.x];
        ts[threadIdx.x] = s;
    }
    __syncthreads();

    float acc = 0.0f;
#pragma unroll 4
    for (int i = 0; i < IDIM / DSPL; ++i)
        acc += ts[i] * __ldg(&Wo[(size_t)(i0 + i) * DIM + o]);
    g_yp[(b * DSPL + is) * DIM + o] = acc;
}

// ---------------------------------------------------------------------------
// K4: finalize y.  grid (DIM/256, BATCH), 256 threads
// ---------------------------------------------------------------------------
__global__ void k_finy() {
    const int o = blockIdx.x * 256 + threadIdx.x;
    const int b = blockIdx.y;
    float s = 0.0f;
#pragma unroll
    for (int p = 0; p < DSPL; ++p)
        s += g_yp[(b * DSPL + p) * DIM + o];
    g_y[b * DIM + o] = s;
}

// ---------------------------------------------------------------------------
// K5: broadcast y[b] into every sequence row of the output (float4 stores).
//     Total B*S*D/4 = 2,097,152 float4 -> 8192 blocks x 256 threads.
//     Each block covers exactly one (b, s) row: y[b] row stays L1-resident.
// ---------------------------------------------------------------------------
__global__ void k_bcast(float4* __restrict__ out) {
    const size_t idx = (size_t)blockIdx.x * 256 + threadIdx.x;
    const int d4 = (int)(idx & (DIM / 4 - 1));        // 0..255
    const size_t bs = idx >> 8;                       // b*SEQ + s
    const int b = (int)(bs >> 11);                    // SEQ = 2048 = 2^11
    const float4* y4 = reinterpret_cast<const float4*>(g_y);
    out[idx] = __ldg(&y4[b * (DIM / 4) + d4]);
}

// ---------------------------------------------------------------------------
// Inputs (metadata order): 0=inputs_embeds [B,S,D] f32, 1=structure_features,
// 2=Wq, 3=Wk, 4=Wv [D,I] f32, 5=Wo [I,D] f32, 6=num_heads.
// Only x, Wv, Wo matter (softmax collapses to 1/S exactly).
// ---------------------------------------------------------------------------
extern "C" void kernel_launch(void* const* d_in, const int* in_sizes, int n_in,
                              void* d_out, int out_size) {
    (void)in_sizes; (void)n_in; (void)out_size;
    const float* x  = (const float*)d_in[0];
    const float* Wv = (const float*)d_in[4];
    const float* Wo = (const float*)d_in[5];
    float* out = (float*)d_out;

    k_colsum<<<dim3(DIM / 256, NSPLIT, BATCH), 256>>>(x);
    k_gemv1 <<<dim3(IDIM / CH, DSPL, BATCH), CH>>>(Wv);
    k_gemv2 <<<dim3(DIM  / CH, DSPL, BATCH), CH>>>(Wo);
    k_finy  <<<dim3(DIM / 256, BATCH), 256>>>();
    k_bcast <<<(BATCH * SEQ * DIM / 4) / 256, 256>>>((float4*)out);
}

// round 2
// speedup vs baseline: 1.4127x; 1.4127x over previous
#include <cuda_runtime.h>
#include <cuda_bf16.h>
#include <cstddef>

// Problem: B=4, S=2048, D=1024, G=256, I=1024, H=16.
// Algebraic collapse: keys are identical along the key axis -> softmax == 1/S
// exactly -> out[b,s,:] = ((mean_s x[b,s,:]) @ Wv) @ Wo, independent of s.
//
// Single persistent kernel, 128 blocks (<= 152 SMs: wave-1 residency
// guaranteed, so atomic spin grid-barriers cannot deadlock). 4 phases
// separated by 3 grid barriers. Weights are read ONCE each (batched over B).

#define BATCH 4
#define SEQ   2048
#define DIM   1024
#define IDIM  1024
#define NBLK  128
#define NTHR  256
#define SP1   32      // colsum splits (64 rows each)
#define DS    16      // GEMV reduction splits (slice of 64)

// Scratch (__device__ globals; no allocation allowed)
__device__ float g_part[BATCH * SP1 * DIM];   // 512 KB colsum partials
__device__ float g_tp  [BATCH * DS  * IDIM];  // 256 KB gemv1 partials
__device__ float g_yp  [BATCH * DS  * DIM];   // 256 KB gemv2 partials

__device__ unsigned g_bar_cnt[3];
__device__ unsigned g_bar_gen[3];

__device__ __forceinline__ void grid_barrier(int i) {
    __syncthreads();
    if (threadIdx.x == 0) {
        __threadfence();
        unsigned g = *(volatile unsigned*)&g_bar_gen[i];
        unsigned old = atomicAdd(&g_bar_cnt[i], 1u);
        if (old == NBLK - 1) {
            g_bar_cnt[i] = 0;
            __threadfence();
            atomicAdd(&g_bar_gen[i], 1u);
        } else {
            while (*(volatile unsigned*)&g_bar_gen[i] == g) { __nanosleep(64); }
        }
        __threadfence();
    }
    __syncthreads();
}

__global__ void __launch_bounds__(NTHR, 1)
fusion_persistent(const float* __restrict__ x,
                  const float* __restrict__ Wv,
                  const float* __restrict__ Wo,
                  float* __restrict__ out) {
    const int blk = blockIdx.x;
    const int tid = threadIdx.x;
    __shared__ __align__(16) float sbuf[DIM];  // 4 KB, reused per phase

    // ---------------- Phase 1: column-sum partials of x --------------------
    // item = (b, sp): 64 rows x full 1024 cols. 128 items == 128 blocks.
    {
        const int b  = blk >> 5;
        const int sp = blk & 31;
        const float4* xp = reinterpret_cast<const float4*>(x)
                         + ((size_t)(b * SEQ + sp * 64) * DIM) / 4 + tid;
        float4 acc = make_float4(0.f, 0.f, 0.f, 0.f);
#pragma unroll 16
        for (int r = 0; r < 64; ++r) {
            float4 v = xp[(size_t)r * (DIM / 4)];
            acc.x += v.x; acc.y += v.y; acc.z += v.z; acc.w += v.w;
        }
        reinterpret_cast<float4*>(g_part)[((b * SP1 + sp) * DIM) / 4 + tid] = acc;
    }
    grid_barrier(0);

    // ---------------- Phase 2: t_partial = xbar-slice @ Wv (all batches) ---
    // 64 items: (ds, ic). d-slice of 64, i-chunk of 256. Wv read ONCE.
    if (blk < 64) {
        const int ds = blk >> 2;
        const int ic = blk & 3;
        const int d0 = ds * 64;
        const int i  = ic * 256 + tid;

        // sbuf[bb*64+dd] = xbar[bb][d0+dd]  (reduce 32 colsum partials, L2 hits)
        {
            const int bb = tid >> 6, dd = tid & 63;
            float s = 0.f;
#pragma unroll
            for (int sp = 0; sp < SP1; ++sp)
                s += g_part[(bb * SP1 + sp) * DIM + d0 + dd];
            sbuf[tid] = s * (1.0f / (float)SEQ);
        }
        __syncthreads();

        float a0 = 0.f, a1 = 0.f, a2 = 0.f, a3 = 0.f;
#pragma unroll 8
        for (int d = 0; d < 64; ++d) {
            float w = __ldg(&Wv[(size_t)(d0 + d) * IDIM + i]);
            a0 += sbuf[d]       * w;
            a1 += sbuf[64 + d]  * w;
            a2 += sbuf[128 + d] * w;
            a3 += sbuf[192 + d] * w;
        }
        g_tp[(0 * DS + ds) * IDIM + i] = a0;
        g_tp[(1 * DS + ds) * IDIM + i] = a1;
        g_tp[(2 * DS + ds) * IDIM + i] = a2;
        g_tp[(3 * DS + ds) * IDIM + i] = a3;
    }
    grid_barrier(1);

    // ---------------- Phase 3: y_partial = t-slice @ Wo (all batches) ------
    if (blk < 64) {
        const int is = blk >> 2;
        const int ic = blk & 3;
        const int i0 = is * 64;
        const int o  = ic * 256 + tid;

        {
            const int bb = tid >> 6, ii = tid & 63;
            float s = 0.f;
#pragma unroll
            for (int p = 0; p < DS; ++p)
                s += g_tp[(bb * DS + p) * IDIM + i0 + ii];
            sbuf[tid] = s;
        }
        __syncthreads();

        float a0 = 0.f, a1 = 0.f, a2 = 0.f, a3 = 0.f;
#pragma unroll 8
        for (int i = 0; i < 64; ++i) {
            float w = __ldg(&Wo[(size_t)(i0 + i) * DIM + o]);
            a0 += sbuf[i]       * w;
            a1 += sbuf[64 + i]  * w;
            a2 += sbuf[128 + i] * w;
            a3 += sbuf[192 + i] * w;
        }
        g_yp[(0 * DS + is) * DIM + o] = a0;
        g_yp[(1 * DS + is) * DIM + o] = a1;
        g_yp[(2 * DS + is) * DIM + o] = a2;
        g_yp[(3 * DS + is) * DIM + o] = a3;
    }
    grid_barrier(2);

    // ---------------- Phase 4: finalize y + broadcast to all 2048 rows -----
    // item = (b, sblock of 64 rows). Each block builds y[b] (1024 f) in smem,
    // then every thread stores its one float4 64 times (register-resident).
    {
        const int b  = blk >> 5;
        const int sb = blk & 31;

#pragma unroll
        for (int k = 0; k < 4; ++k) {
            const int o = k * 256 + tid;
            float s = 0.f;
#pragma unroll
            for (int p = 0; p < DS; ++p)
                s += g_yp[(b * DS + p) * DIM + o];
            sbuf[o] = s;
        }
        __syncthreads();

        const float4 v = reinterpret_cast<const float4*>(sbuf)[tid];
        float4* o4 = reinterpret_cast<float4*>(out)
                   + ((size_t)(b * SEQ + sb * 64) * DIM) / 4 + tid;
#pragma unroll 8
        for (int r = 0; r < 64; ++r)
            o4[(size_t)r * (DIM / 4)] = v;
    }
}

// Inputs (metadata order): 0=inputs_embeds [B,S,D] f32, 1=structure_features,
// 2=Wq, 3=Wk, 4=Wv [D,I] f32, 5=Wo [I,D] f32, 6=num_heads.
extern "C" void kernel_launch(void* const* d_in, const int* in_sizes, int n_in,
                              void* d_out, int out_size) {
    (void)in_sizes; (void)n_in; (void)out_size;
    const float* x  = (const float*)d_in[0];
    const float* Wv = (const float*)d_in[4];
    const float* Wo = (const float*)d_in[5];
    fusion_persistent<<<NBLK, NTHR>>>(x, Wv, Wo, (float*)d_out);
}

// round 3
// speedup vs baseline: 1.8431x; 1.3047x over previous
#include <cuda_runtime.h>
#include <cuda_bf16.h>
#include <cstddef>

// B=4, S=2048, D=1024, I=1024. Softmax collapses to exactly 1/S (keys are
// broadcast-identical), so out[b,s,:] = ((mean_s x[b,s,:]) @ Wv) @ Wo.
// One persistent kernel, 128 blocks x 1024 threads (1 block/SM, co-resident,
// spin grid-barriers safe). 4 phases / 3 barriers. Weights read once.

#define BATCH 4
#define SEQ   2048
#define DIM   1024
#define IDIM  1024
#define NBLK  128
#define NTHR  1024
#define SP1   32     // colsum splits (64 rows each)
#define DS    16     // GEMV reduction splits (d-slice of 64)

__device__ float g_part[BATCH * SP1 * DIM];   // 512 KB
__device__ float g_tp  [BATCH * DS  * IDIM];  // 256 KB
__device__ float g_yp  [BATCH * DS  * DIM];   // 256 KB

__device__ unsigned g_bar_cnt[3];
__device__ unsigned g_bar_gen[3];

__device__ __forceinline__ void grid_barrier(int i) {
    __syncthreads();
    if (threadIdx.x == 0) {
        __threadfence();
        unsigned g = *(volatile unsigned*)&g_bar_gen[i];
        unsigned old = atomicAdd(&g_bar_cnt[i], 1u);
        if (old == NBLK - 1) {
            g_bar_cnt[i] = 0;
            __threadfence();
            atomicAdd(&g_bar_gen[i], 1u);
        } else {
            while (*(volatile unsigned*)&g_bar_gen[i] == g) { __nanosleep(32); }
        }
        __threadfence();
    }
    __syncthreads();
}

__global__ void __launch_bounds__(NTHR, 1)
fusion_persistent(const float* __restrict__ x,
                  const float* __restrict__ Wv,
                  const float* __restrict__ Wo,
                  float* __restrict__ out) {
    const int blk = blockIdx.x;
    const int tid = threadIdx.x;

    __shared__ __align__(16) float s_red[4096];  // 16 KB reduce buffer
    __shared__ float s_xs[256];                  // gathered activations

    // ---------------- Phase 1: column-sum partials of x --------------------
    // Block = (b, sp): 64 rows x 1024 cols. Threads: (r4 = tid>>8, c = tid&255)
    // -> 4 rows in flight, 16 independent float4 loads each.
    {
        const int b  = blk >> 5;
        const int sp = blk & 31;
        const int r4 = tid >> 8;
        const int c  = tid & 255;
        const float4* xp = reinterpret_cast<const float4*>(x)
                         + (size_t)(b * SEQ + sp * 64 + r4) * 256 + c;
        float4 acc = make_float4(0.f, 0.f, 0.f, 0.f);
#pragma unroll
        for (int r = 0; r < 16; ++r) {
            float4 v = xp[(size_t)r * 4 * 256];
            acc.x += v.x; acc.y += v.y; acc.z += v.z; acc.w += v.w;
        }
        float4* sb4 = reinterpret_cast<float4*>(s_red);
        sb4[tid] = acc;
        __syncthreads();
        if (tid < 256) {
            float4 a = sb4[tid], b1 = sb4[tid + 256],
                   c1 = sb4[tid + 512], d1 = sb4[tid + 768];
            float4 s = make_float4(a.x + b1.x + c1.x + d1.x,
                                   a.y + b1.y + c1.y + d1.y,
                                   a.z + b1.z + c1.z + d1.z,
                                   a.w + b1.w + c1.w + d1.w);
            reinterpret_cast<float4*>(g_part)[(b * SP1 + sp) * 256 + tid] = s;
        }
    }
    grid_barrier(0);

    // ---------------- Phase 2: t = xbar @ Wv (all batches, Wv read once) ---
    // Block = (ds, ic): d-slice of 64, i-chunk of 128. 16*8 = 128 blocks.
    {
        const int ds = blk >> 3;
        const int ic = blk & 7;
        const int d0 = ds * 64;

        if (tid < 256) {                       // xbar[bb][d0+dd], bb=tid>>6
            const int bb = tid >> 6, dd = tid & 63;
            float s = 0.f;
#pragma unroll
            for (int sp = 0; sp < SP1; ++sp)
                s += g_part[(bb * SP1 + sp) * DIM + d0 + dd];
            s_xs[tid] = s * (1.0f / (float)SEQ);
        }
        __syncthreads();

        const int dg = tid >> 7;               // 0..7 d-subgroup
        const int il = tid & 127;
        const int i  = ic * 128 + il;
        float a0 = 0.f, a1 = 0.f, a2 = 0.f, a3 = 0.f;
#pragma unroll
        for (int dd = 0; dd < 8; ++dd) {
            const int dl = dg * 8 + dd;
            const float w = __ldg(&Wv[(size_t)(d0 + dl) * IDIM + i]);
            a0 += s_xs[dl]       * w;
            a1 += s_xs[64 + dl]  * w;
            a2 += s_xs[128 + dl] * w;
            a3 += s_xs[192 + dl] * w;
        }
        s_red[(0 * 8 + dg) * 128 + il] = a0;
        s_red[(1 * 8 + dg) * 128 + il] = a1;
        s_red[(2 * 8 + dg) * 128 + il] = a2;
        s_red[(3 * 8 + dg) * 128 + il] = a3;
        __syncthreads();
        if (tid < 512) {
            const int bb = tid >> 7, il2 = tid & 127;
            float s = 0.f;
#pragma unroll
            for (int g = 0; g < 8; ++g)
                s += s_red[(bb * 8 + g) * 128 + il2];
            g_tp[(bb * DS + ds) * IDIM + ic * 128 + il2] = s;
        }
    }
    grid_barrier(1);

    // ---------------- Phase 3: y = t @ Wo (all batches, Wo read once) ------
    {
        const int is = blk >> 3;
        const int ic = blk & 7;
        const int i0 = is * 64;

        if (tid < 256) {
            const int bb = tid >> 6, ii = tid & 63;
            float s = 0.f;
#pragma unroll
            for (int p = 0; p < DS; ++p)
                s += g_tp[(bb * DS + p) * IDIM + i0 + ii];
            s_xs[tid] = s;
        }
        __syncthreads();

        const int ig = tid >> 7;
        const int ol = tid & 127;
        const int o  = ic * 128 + ol;
        float a0 = 0.f, a1 = 0.f, a2 = 0.f, a3 = 0.f;
#pragma unroll
        for (int ii = 0; ii < 8; ++ii) {
            const int il = ig * 8 + ii;
            const float w = __ldg(&Wo[(size_t)(i0 + il) * DIM + o]);
            a0 += s_xs[il]       * w;
            a1 += s_xs[64 + il]  * w;
            a2 += s_xs[128 + il] * w;
            a3 += s_xs[192 + il] * w;
        }
        __syncthreads();  // s_red reuse
        s_red[(0 * 8 + ig) * 128 + ol] = a0;
        s_red[(1 * 8 + ig) * 128 + ol] = a1;
        s_red[(2 * 8 + ig) * 128 + ol] = a2;
        s_red[(3 * 8 + ig) * 128 + ol] = a3;
        __syncthreads();
        if (tid < 512) {
            const int bb = tid >> 7, ol2 = tid & 127;
            float s = 0.f;
#pragma unroll
            for (int g = 0; g < 8; ++g)
                s += s_red[(bb * 8 + g) * 128 + ol2];
            g_yp[(bb * DS + is) * DIM + ic * 128 + ol2] = s;
        }
    }
    grid_barrier(2);

    // ---------------- Phase 4: finalize y[b] + broadcast 64 rows -----------
    {
        const int b  = blk >> 5;
        const int sb = blk & 31;

        float s = 0.f;
#pragma unroll
        for (int p = 0; p < DS; ++p)
            s += g_yp[(b * DS + p) * DIM + tid];
        s_red[tid] = s;
        __syncthreads();

        const int r4 = tid >> 8;
        const int c  = tid & 255;
        const float4 v = reinterpret_cast<const float4*>(s_red)[c];
        float4* o4 = reinterpret_cast<float4*>(out)
                   + (size_t)(b * SEQ + sb * 64 + r4) * 256 + c;
#pragma unroll
        for (int r = 0; r < 16; ++r)
            o4[(size_t)r * 4 * 256] = v;
    }
}

// Inputs: 0=inputs_embeds [B,S,D] f32, 1=structure_features, 2=Wq, 3=Wk,
// 4=Wv [D,I] f32, 5=Wo [I,D] f32, 6=num_heads. Only x, Wv, Wo matter.
extern "C" void kernel_launch(void* const* d_in, const int* in_sizes, int n_in,
                              void* d_out, int out_size) {
    (void)in_sizes; (void)n_in; (void)out_size;
    const float* x  = (const float*)d_in[0];
    const float* Wv = (const float*)d_in[4];
    const float* Wo = (const float*)d_in[5];
    fusion_persistent<<<NBLK, NTHR>>>(x, Wv, Wo, (float*)d_out);
}